// round 16
// baseline (speedup 1.0000x reference)
#include <cuda_runtime.h>
#include <cuda_bf16.h>
#include <math.h>

// Shapes (fixed): B=8, L=1024, D=1024, H=8, DH=128, BH=64
#define N_B    8
#define N_L    1024
#define N_D    1024
#define SCALE_F 0.25f
#define EPS_F   1e-5f
#define LOG2E_F 1.4426950408889634f

// ---------------------------------------------------------------------------
// Scratch
// ---------------------------------------------------------------------------
__device__ float g_x[8u * 1024u * 1024u];     // embedded input (f32, residual)
__device__ float g_nb[8 * 1024];              // -inf mask bias
__device__ float g_pmx[8 * 8 * 1024];         // pool partial max [b][slice][d]
__device__ float g_psm[8 * 8 * 1024];         // pool partial sum

__device__ __nv_bfloat16 g_xb[8u * 1024u * 1024u];   // x bf16
__device__ __nv_bfloat16 g_qb[8u * 1024u * 1024u];   // Q bf16
__device__ __nv_bfloat16 g_kb[8u * 1024u * 1024u];   // K bf16
__device__ __nv_bfloat16 g_vb[8u * 1024u * 1024u];   // V bf16
__device__ __nv_bfloat16 g_cb[8u * 1024u * 1024u];   // ctx bf16
__device__ __nv_bfloat16 g_wq[1024 * 1024];
__device__ __nv_bfloat16 g_wk[1024 * 1024];
__device__ __nv_bfloat16 g_wv[1024 * 1024];
__device__ __nv_bfloat16 g_wo[1024 * 1024];

// ---------------------------------------------------------------------------
// Helpers
// ---------------------------------------------------------------------------
__device__ __forceinline__ void cpa16(void* dst_smem, const void* src_gmem) {
    unsigned d = (unsigned)__cvta_generic_to_shared(dst_smem);
    asm volatile("cp.async.cg.shared.global [%0], [%1], 16;\n"
                 :: "r"(d), "l"(src_gmem));
}

__device__ __forceinline__ float blockSum(float v) {
    __shared__ float sh[32];
    int lane = threadIdx.x & 31, wid = threadIdx.x >> 5;
    #pragma unroll
    for (int o = 16; o > 0; o >>= 1) v += __shfl_xor_sync(0xffffffffu, v, o);
    if (lane == 0) sh[wid] = v;
    __syncthreads();
    int nw = blockDim.x >> 5;
    float r = (threadIdx.x < (unsigned)nw) ? sh[threadIdx.x] : 0.0f;
    if (wid == 0) {
        #pragma unroll
        for (int o = 16; o > 0; o >>= 1) r += __shfl_xor_sync(0xffffffffu, r, o);
        if (lane == 0) sh[0] = r;
    }
    __syncthreads();
    float out = sh[0];
    __syncthreads();
    return out;
}

// ---------------------------------------------------------------------------
// Embedding (f32 + bf16) + mask + fused 4-weight convert
// ---------------------------------------------------------------------------
__global__ void embed_kernel(const int* __restrict__ tokens,
                             const float* __restrict__ emb,
                             float* __restrict__ x,
                             __nv_bfloat16* __restrict__ xb) {
    int row = blockIdx.x;
    int tok = tokens[row];
    float4 v = ((const float4*)(emb + (long)tok * N_D))[threadIdx.x];
    ((float4*)(x + (long)row * N_D))[threadIdx.x] = v;
    __nv_bfloat162* db = (__nv_bfloat162*)(xb + (long)row * N_D);
    db[2 * threadIdx.x]     = __nv_bfloat162(__float2bfloat16(v.x), __float2bfloat16(v.y));
    db[2 * threadIdx.x + 1] = __nv_bfloat162(__float2bfloat16(v.z), __float2bfloat16(v.w));
}

__global__ void mask_kernel(const int* __restrict__ tokens, float* __restrict__ nb) {
    int i = blockIdx.x * blockDim.x + threadIdx.x;
    nb[i] = (tokens[i] == 0) ? -INFINITY : 0.0f;
}

__global__ void conv4_kernel(const float* __restrict__ s0, const float* __restrict__ s1,
                             const float* __restrict__ s2, const float* __restrict__ s3,
                             __nv_bfloat16* __restrict__ d0, __nv_bfloat16* __restrict__ d1,
                             __nv_bfloat16* __restrict__ d2, __nv_bfloat16* __restrict__ d3) {
    int w = blockIdx.x >> 11;
    const float* src = (w == 0) ? s0 : (w == 1) ? s1 : (w == 2) ? s2 : s3;
    __nv_bfloat16* dst = (w == 0) ? d0 : (w == 1) ? d1 : (w == 2) ? d2 : d3;
    int i = (blockIdx.x & 2047) * blockDim.x + threadIdx.x;
    float2 v = ((const float2*)src)[i];
    ((__nv_bfloat162*)dst)[i] = __nv_bfloat162(__float2bfloat16(v.x), __float2bfloat16(v.y));
}

// ---------------------------------------------------------------------------
// bf16 MMA + ldmatrix
// ---------------------------------------------------------------------------
#define MMA_BF16(d, a, b)                                                     \
    asm volatile(                                                             \
        "mma.sync.aligned.m16n8k16.row.col.f32.bf16.bf16.f32 "                \
        "{%0,%1,%2,%3},{%4,%5,%6,%7},{%8,%9},{%0,%1,%2,%3};"                  \
        : "+f"((d)[0]), "+f"((d)[1]), "+f"((d)[2]), "+f"((d)[3])              \
        : "r"((a)[0]), "r"((a)[1]), "r"((a)[2]), "r"((a)[3]),                 \
          "r"((b)[0]), "r"((b)[1]))

#define LDSM_X4(r0, r1, r2, r3, addr)                                         \
    asm volatile("ldmatrix.sync.aligned.m8n8.x4.shared.b16 {%0,%1,%2,%3}, [%4];" \
                 : "=r"(r0), "=r"(r1), "=r"(r2), "=r"(r3) : "r"(addr))

#define LDSM_X4T(r0, r1, r2, r3, addr)                                        \
    asm volatile("ldmatrix.sync.aligned.m8n8.x4.trans.shared.b16 {%0,%1,%2,%3}, [%4];" \
                 : "=r"(r0), "=r"(r1), "=r"(r2), "=r"(r3) : "r"(addr))

// ---------------------------------------------------------------------------
// GEMM SMEM geometry: 128x128 tile, K-chunk 32, 3-stage ring (occ-3 config)
// ---------------------------------------------------------------------------
#define A_LDH   40
#define BNN_LDH 136
#define A_H     (128 * A_LDH)
#define B_H     5120
#define STG_H   (A_H + B_H)               // 9472 halves = 18944 B
#define NSTG    3
#define SMEM_BYTES (NSTG * STG_H * 2)     // 56832 B -> 3 CTAs/SM

// Shared mainloop: 128x128 tile into acc[4][4][4], warp tile 64x32.
// Single barrier per k-tile; prefetch target (kt+2)%3 == (kt-1)%3 (retired).
#define GEMM_MAINLOOP(Aptr, Bptr, row0, col0, K)                              \
    int KT = (K) >> 5;                                                        \
    auto load_tile = [&](int kt, int buf) {                                   \
        __nv_bfloat16* Asb = sm + buf * STG_H;                                \
        __nv_bfloat16* Bsb = Asb + A_H;                                       \
        int k0 = kt << 5;                                                     \
        _Pragma("unroll")                                                     \
        for (int p = 0; p < 2; p++) {                                         \
            int idx = p * 256 + tid;                                          \
            int rr = idx >> 2, cc = (idx & 3) << 3;                           \
            cpa16(Asb + rr * A_LDH + cc, (Aptr) + (long)((row0) + rr) * (K) + k0 + cc); \
        }                                                                     \
        _Pragma("unroll")                                                     \
        for (int p = 0; p < 2; p++) {                                         \
            int idx = p * 256 + tid;                                          \
            int rr = idx >> 4, cc = (idx & 15) << 3;                          \
            cpa16(Bsb + rr * BNN_LDH + cc, (Bptr) + (long)(k0 + rr) * 1024 + (col0) + cc); \
        }                                                                     \
    };                                                                        \
    float acc[4][4][4];                                                       \
    _Pragma("unroll")                                                         \
    for (int i = 0; i < 4; i++)                                               \
        _Pragma("unroll")                                                     \
        for (int j = 0; j < 4; j++)                                           \
            _Pragma("unroll")                                                 \
            for (int t = 0; t < 4; t++) acc[i][j][t] = 0.0f;                  \
    load_tile(0, 0);                                                          \
    asm volatile("cp.async.commit_group;\n" ::);                              \
    load_tile(1, 1);                                                          \
    asm volatile("cp.async.commit_group;\n" ::);                              \
    for (int kt = 0; kt < KT; kt++) {                                         \
        asm volatile("cp.async.wait_group 1;\n" ::);                          \
        __syncthreads();                                                      \
        int pf = kt + 2;                                                      \
        if (pf < KT) load_tile(pf, pf % 3);                                   \
        asm volatile("cp.async.commit_group;\n" ::);                          \
        __nv_bfloat16* Asb = sm + (kt % 3) * STG_H;                           \
        unsigned AsU = (unsigned)__cvta_generic_to_shared(Asb);               \
        unsigned BsU = (unsigned)__cvta_generic_to_shared(Asb + A_H);         \
        _Pragma("unroll")                                                     \
        for (int ks = 0; ks < 2; ks++) {                                      \
            int k0h = ks * 16;                                                \
            unsigned afr[4][4];                                               \
            _Pragma("unroll")                                                 \
            for (int i = 0; i < 4; i++) {                                     \
                int rr = warpRow * 64 + i * 16 + (lane & 15);                 \
                unsigned ad = AsU + (rr * A_LDH + k0h + ((lane >> 4) << 3)) * 2; \
                LDSM_X4(afr[i][0], afr[i][1], afr[i][2], afr[i][3], ad);      \
            }                                                                 \
            unsigned bfr[4][2];                                               \
            _Pragma("unroll")                                                 \
            for (int j2 = 0; j2 < 2; j2++) {                                  \
                int n0 = warpCol * 32 + j2 * 16;                              \
                int rr = k0h + (((lane >> 3) & 1) << 3) + (lane & 7);         \
                int cc = n0 + ((lane >> 4) << 3);                             \
                unsigned ad = BsU + (rr * BNN_LDH + cc) * 2;                  \
                LDSM_X4T(bfr[2 * j2][0], bfr[2 * j2][1],                      \
                         bfr[2 * j2 + 1][0], bfr[2 * j2 + 1][1], ad);         \
            }                                                                 \
            _Pragma("unroll")                                                 \
            for (int i = 0; i < 4; i++)                                       \
                _Pragma("unroll")                                             \
                for (int j = 0; j < 4; j++)                                   \
                    MMA_BF16(acc[i][j], afr[i], bfr[j]);                      \
        }                                                                     \
    }

// ---------------------------------------------------------------------------
// Fused QKV GEMM: z selects (W, bias, C); bf16 output. 128x128 tile, occ 3.
// ---------------------------------------------------------------------------
__global__ void __launch_bounds__(256, 3)
gemm_qkv(const __nv_bfloat16* __restrict__ A,
         const __nv_bfloat16* B0, const __nv_bfloat16* B1, const __nv_bfloat16* B2,
         const float* bias0, const float* bias1, const float* bias2,
         __nv_bfloat16* C0, __nv_bfloat16* C1, __nv_bfloat16* C2) {
    extern __shared__ __nv_bfloat16 sm[];
    int z = blockIdx.z;
    const __nv_bfloat16* B = (z == 0) ? B0 : (z == 1) ? B1 : B2;
    const float* bias      = (z == 0) ? bias0 : (z == 1) ? bias1 : bias2;
    __nv_bfloat16* C       = (z == 0) ? C0 : (z == 1) ? C1 : C2;

    int tid = threadIdx.x;
    int lane = tid & 31, wid = tid >> 5;
    int warpRow = wid >> 2, warpCol = wid & 3;
    int grp = lane >> 2, qid = lane & 3;
    int row0 = blockIdx.y * 128;
    int col0 = blockIdx.x * 128;

    GEMM_MAINLOOP(A, B, row0, col0, 1024)

    #pragma unroll
    for (int i = 0; i < 4; i++) {
        int r = row0 + warpRow * 64 + i * 16 + grp;
        #pragma unroll
        for (int j = 0; j < 4; j++) {
            int c = col0 + warpCol * 32 + j * 8 + 2 * qid;
            float2 bb = *(const float2*)(bias + c);
            *(__nv_bfloat162*)(C + (long)r * 1024 + c) =
                __floats2bfloat162_rn(acc[i][j][0] + bb.x, acc[i][j][1] + bb.y);
            *(__nv_bfloat162*)(C + (long)(r + 8) * 1024 + c) =
                __floats2bfloat162_rn(acc[i][j][2] + bb.x, acc[i][j][3] + bb.y);
        }
    }
}

// ---------------------------------------------------------------------------
// Wo GEMM + residual + fused pooling partials (r never hits gmem).
//   128x128 tile; grid (8, 64); blockIdx.y: b = y>>3, slice = y&7. occ 3.
// ---------------------------------------------------------------------------
__global__ void __launch_bounds__(256, 3)
gemm_wo_pool(const __nv_bfloat16* __restrict__ A, const __nv_bfloat16* __restrict__ B,
             const float* __restrict__ bias, const float* __restrict__ res,
             float* __restrict__ pmx, float* __restrict__ psm) {
    extern __shared__ __nv_bfloat16 sm[];

    int tid = threadIdx.x;
    int lane = tid & 31, wid = tid >> 5;
    int warpRow = wid >> 2, warpCol = wid & 3;
    int grp = lane >> 2, qid = lane & 3;
    int row0 = blockIdx.y * 128;
    int col0 = blockIdx.x * 128;

    GEMM_MAINLOOP(A, B, row0, col0, 1024)

    // epilogue: v = acc + bias + res; per-column (max,sum) over 128 rows
    __syncthreads();                       // tile ring no longer in use
    float* sPm = (float*)sm;               // [2][128]
    float* sPs = (float*)sm + 256;         // [2][128]

    #pragma unroll
    for (int j = 0; j < 4; j++) {
        int c = col0 + warpCol * 32 + j * 8 + 2 * qid;
        float2 bb = *(const float2*)(bias + c);
        float m0 = -INFINITY, m1 = -INFINITY, s0 = 0.0f, s1 = 0.0f;
        #pragma unroll
        for (int i = 0; i < 4; i++) {
            int r = row0 + warpRow * 64 + i * 16 + grp;
            float2 r0v = *(const float2*)(res + (long)r * 1024 + c);
            float2 r1v = *(const float2*)(res + (long)(r + 8) * 1024 + c);
            float v00 = acc[i][j][0] + bb.x + r0v.x;
            float v01 = acc[i][j][1] + bb.y + r0v.y;
            float v10 = acc[i][j][2] + bb.x + r1v.x;
            float v11 = acc[i][j][3] + bb.y + r1v.y;
            m0 = fmaxf(m0, fmaxf(v00, v10));
            m1 = fmaxf(m1, fmaxf(v01, v11));
            s0 += v00 + v10;
            s1 += v01 + v11;
        }
        // reduce over grp (lane bits 2..4)
        #pragma unroll
        for (int o = 4; o <= 16; o <<= 1) {
            m0 = fmaxf(m0, __shfl_xor_sync(0xffffffffu, m0, o));
            m1 = fmaxf(m1, __shfl_xor_sync(0xffffffffu, m1, o));
            s0 += __shfl_xor_sync(0xffffffffu, s0, o);
            s1 += __shfl_xor_sync(0xffffffffu, s1, o);
        }
        if (grp == 0) {
            int lc = warpCol * 32 + j * 8 + 2 * qid;
            sPm[warpRow * 128 + lc]     = m0;
            sPm[warpRow * 128 + lc + 1] = m1;
            sPs[warpRow * 128 + lc]     = s0;
            sPs[warpRow * 128 + lc + 1] = s1;
        }
    }
    __syncthreads();

    if (tid < 128) {
        int b = blockIdx.y >> 3, sl = blockIdx.y & 7;
        float m = fmaxf(sPm[tid], sPm[128 + tid]);
        float s = sPs[tid] + sPs[128 + tid];
        long o = (((long)(b << 3) + sl) << 10) + col0 + tid;
        pmx[o] = m;
        psm[o] = s;
    }
}

// ---------------------------------------------------------------------------
// Fused flash attention, 64-row KV tiles, 2 CTAs/SM (unchanged)
// ---------------------------------------------------------------------------
#define FL_LDH     136
#define FL_Q_H     (128 * FL_LDH)
#define FL_KV_H    (64 * FL_LDH)
#define FL_SMEM    ((FL_Q_H + 4 * FL_KV_H) * 2)

__global__ void __launch_bounds__(256, 2)
flash_kernel(const __nv_bfloat16* __restrict__ Q,
             const __nv_bfloat16* __restrict__ K,
             const __nv_bfloat16* __restrict__ V,
             const float* __restrict__ nb,
             __nv_bfloat16* __restrict__ Octx) {
    extern __shared__ __nv_bfloat16 fsm[];
    __nv_bfloat16* Qs = fsm;
    __nv_bfloat16* Ks = fsm + FL_Q_H;
    __nv_bfloat16* Vs = fsm + FL_Q_H + 2 * FL_KV_H;

    int tid = threadIdx.x;
    int lane = tid & 31, wid = tid >> 5;
    int grp = lane >> 2, qid = lane & 3;
    int m0 = wid * 16;

    int bh = blockIdx.y;
    int q0 = blockIdx.x * 128;
    const __nv_bfloat16* Qg = Q + (long)bh * 131072 + (long)q0 * 128;
    const __nv_bfloat16* Kg = K + (long)bh * 131072;
    const __nv_bfloat16* Vg = V + (long)bh * 131072;
    const float* nbr = nb + ((bh & 7) << 10);
    __nv_bfloat16* Cg = Octx + (long)bh * 131072 + (long)q0 * 128;

    auto loadKV = [&](int kt, int stg) {
        const __nv_bfloat16* Kt = Kg + (long)kt * 8192;
        const __nv_bfloat16* Vt = Vg + (long)kt * 8192;
        __nv_bfloat16* Kd = Ks + stg * FL_KV_H;
        __nv_bfloat16* Vd = Vs + stg * FL_KV_H;
        #pragma unroll
        for (int p = 0; p < 4; p++) {
            int idx = p * 256 + tid;
            int r = idx >> 4, cc = (idx & 15) << 3;
            cpa16(Kd + r * FL_LDH + cc, Kt + r * 128 + cc);
        }
        #pragma unroll
        for (int p = 0; p < 4; p++) {
            int idx = p * 256 + tid;
            int r = idx >> 4, cc = (idx & 15) << 3;
            cpa16(Vd + r * FL_LDH + cc, Vt + r * 128 + cc);
        }
    };

    #pragma unroll
    for (int p = 0; p < 8; p++) {
        int idx = p * 256 + tid;
        int r = idx >> 4, cc = (idx & 15) << 3;
        cpa16(Qs + r * FL_LDH + cc, Qg + r * 128 + cc);
    }
    loadKV(0, 0);
    asm volatile("cp.async.commit_group;\n" ::);

    float o[16][4];
    #pragma unroll
    for (int j = 0; j < 16; j++)
        #pragma unroll
        for (int t = 0; t < 4; t++) o[j][t] = 0.0f;
    float mrow0 = -1e30f, mrow1 = -1e30f;
    float lrow0 = 0.0f,  lrow1 = 0.0f;

    unsigned QsU = (unsigned)__cvta_generic_to_shared(Qs);

    #pragma unroll 1
    for (int kt = 0; kt < 16; kt++) {
        int stg = kt & 1;
        if (kt < 15) loadKV(kt + 1, stg ^ 1);
        asm volatile("cp.async.commit_group;\n" ::);
        asm volatile("cp.async.wait_group 1;\n" ::);
        __syncthreads();

        unsigned KsU = (unsigned)__cvta_generic_to_shared(Ks + stg * FL_KV_H);
        unsigned VsU = (unsigned)__cvta_generic_to_shared(Vs + stg * FL_KV_H);

        float s[8][4];
        #pragma unroll
        for (int j = 0; j < 8; j++)
            #pragma unroll
            for (int t = 0; t < 4; t++) s[j][t] = 0.0f;

        #pragma unroll
        for (int kf = 0; kf < 8; kf++) {
            unsigned aq[4];
            {
                int r = m0 + (lane & 15);
                int c = kf * 16 + ((lane >> 4) << 3);
                LDSM_X4(aq[0], aq[1], aq[2], aq[3], QsU + (r * FL_LDH + c) * 2);
            }
            #pragma unroll
            for (int j2 = 0; j2 < 4; j2++) {
                unsigned bq[4];
                int rn = j2 * 16 + ((lane >> 4) << 3) + (lane & 7);
                int ck = kf * 16 + (((lane >> 3) & 1) << 3);
                LDSM_X4(bq[0], bq[1], bq[2], bq[3], KsU + (rn * FL_LDH + ck) * 2);
                MMA_BF16(s[2 * j2],     aq, bq);
                MMA_BF16(s[2 * j2 + 1], aq, (bq + 2));
            }
        }

        int kb = kt << 6;
        float mx0 = mrow0, mx1 = mrow1;
        #pragma unroll
        for (int j = 0; j < 8; j++) {
            float2 msk = *(const float2*)(nbr + kb + j * 8 + 2 * qid);
            s[j][0] = fmaf(s[j][0], SCALE_F, msk.x);
            s[j][1] = fmaf(s[j][1], SCALE_F, msk.y);
            s[j][2] = fmaf(s[j][2], SCALE_F, msk.x);
            s[j][3] = fmaf(s[j][3], SCALE_F, msk.y);
            mx0 = fmaxf(mx0, fmaxf(s[j][0], s[j][1]));
            mx1 = fmaxf(mx1, fmaxf(s[j][2], s[j][3]));
        }
        mx0 = fmaxf(mx0, __shfl_xor_sync(0xffffffffu, mx0, 1));
        mx0 = fmaxf(mx0, __shfl_xor_sync(0xffffffffu, mx0, 2));
        mx1 = fmaxf(mx1, __shfl_xor_sync(0xffffffffu, mx1, 1));
        mx1 = fmaxf(mx1, __shfl_xor_sync(0xffffffffu, mx1, 2));

        float al0 = exp2f((mrow0 - mx0) * LOG2E_F);
        float al1 = exp2f((mrow1 - mx1) * LOG2E_F);
        mrow0 = mx0; mrow1 = mx1;

        float r0 = 0.0f, r1 = 0.0f;
        #pragma unroll
        for (int j = 0; j < 8; j++) {
            s[j][0] = exp2f((s[j][0] - mx0) * LOG2E_F);
            s[j][1] = exp2f((s[j][1] - mx0) * LOG2E_F);
            s[j][2] = exp2f((s[j][2] - mx1) * LOG2E_F);
            s[j][3] = exp2f((s[j][3] - mx1) * LOG2E_F);
            r0 += s[j][0] + s[j][1];
            r1 += s[j][2] + s[j][3];
        }
        #pragma unroll
        for (int j = 0; j < 16; j++) {
            o[j][0] *= al0; o[j][1] *= al0;
            o[j][2] *= al1; o[j][3] *= al1;
        }
        lrow0 = lrow0 * al0 + r0;
        lrow1 = lrow1 * al1 + r1;

        #pragma unroll
        for (int t = 0; t < 4; t++) {
            unsigned ap[4];
            __nv_bfloat162 p0 = __floats2bfloat162_rn(s[2 * t][0],     s[2 * t][1]);
            __nv_bfloat162 p1 = __floats2bfloat162_rn(s[2 * t][2],     s[2 * t][3]);
            __nv_bfloat162 p2 = __floats2bfloat162_rn(s[2 * t + 1][0], s[2 * t + 1][1]);
            __nv_bfloat162 p3 = __floats2bfloat162_rn(s[2 * t + 1][2], s[2 * t + 1][3]);
            ap[0] = *(unsigned*)&p0;
            ap[1] = *(unsigned*)&p1;
            ap[2] = *(unsigned*)&p2;
            ap[3] = *(unsigned*)&p3;
            #pragma unroll
            for (int j2 = 0; j2 < 8; j2++) {
                unsigned bv[4];
                int rk = t * 16 + (((lane >> 3) & 1) << 3) + (lane & 7);
                int cn = j2 * 16 + ((lane >> 4) << 3);
                LDSM_X4T(bv[0], bv[1], bv[2], bv[3], VsU + (rk * FL_LDH + cn) * 2);
                MMA_BF16(o[2 * j2],     ap, bv);
                MMA_BF16(o[2 * j2 + 1], ap, (bv + 2));
            }
        }
        __syncthreads();
    }

    lrow0 += __shfl_xor_sync(0xffffffffu, lrow0, 1);
    lrow0 += __shfl_xor_sync(0xffffffffu, lrow0, 2);
    lrow1 += __shfl_xor_sync(0xffffffffu, lrow1, 1);
    lrow1 += __shfl_xor_sync(0xffffffffu, lrow1, 2);
    float inv0 = 1.0f / lrow0;
    float inv1 = 1.0f / lrow1;

    int r0i = m0 + grp, r1i = m0 + grp + 8;
    #pragma unroll
    for (int j = 0; j < 16; j++) {
        int c = j * 8 + 2 * qid;
        *(__nv_bfloat162*)(Cg + (long)r0i * 128 + c) =
            __floats2bfloat162_rn(o[j][0] * inv0, o[j][1] * inv0);
        *(__nv_bfloat162*)(Cg + (long)r1i * 128 + c) =
            __floats2bfloat162_rn(o[j][2] * inv1, o[j][3] * inv1);
    }
}

// ---------------------------------------------------------------------------
// Fused partial-reduce + LayerNorm
// ---------------------------------------------------------------------------
__global__ void __launch_bounds__(256)
ln_kernel(const float* __restrict__ pmx, const float* __restrict__ psm,
          const float* __restrict__ gamma, const float* __restrict__ beta,
          float* __restrict__ out) {
    int b = blockIdx.x, tid = threadIdx.x;
    float av[8];
    #pragma unroll
    for (int i = 0; i < 8; i++) {
        int k = tid + i * 256;
        if (k < 1024) {
            float mx = -INFINITY;
            #pragma unroll
            for (int sl = 0; sl < 8; sl++)
                mx = fmaxf(mx, pmx[(((b << 3) + sl) << 10) + k]);
            av[i] = mx;
        } else {
            int d = k - 1024;
            float sm = 0.0f;
            #pragma unroll
            for (int sl = 0; sl < 8; sl++)
                sm += psm[(((b << 3) + sl) << 10) + d];
            av[i] = sm * (1.0f / 1024.0f);
        }
    }
    float s = 0.0f;
    #pragma unroll
    for (int i = 0; i < 8; i++) s += av[i];
    s = blockSum(s);
    float mu = s * (1.0f / 2048.0f);
    float vs = 0.0f;
    #pragma unroll
    for (int i = 0; i < 8; i++) {
        float d = av[i] - mu;
        vs += d * d;
    }
    vs = blockSum(vs);
    float inv = rsqrtf(vs * (1.0f / 2048.0f) + EPS_F);
    #pragma unroll
    for (int i = 0; i < 8; i++) {
        int k = tid + i * 256;
        out[b * 2048 + k] = (av[i] - mu) * inv * gamma[k] + beta[k];
    }
}

// ---------------------------------------------------------------------------
// Launch
// ---------------------------------------------------------------------------
extern "C" void kernel_launch(void* const* d_in, const int* in_sizes, int n_in,
                              void* d_out, int out_size) {
    const int*   tokens = (const int*)  d_in[0];
    const float* emb    = (const float*)d_in[1];
    const float* Wq     = (const float*)d_in[2];
    const float* bq     = (const float*)d_in[3];
    const float* Wk     = (const float*)d_in[4];
    const float* bk     = (const float*)d_in[5];
    const float* Wv     = (const float*)d_in[6];
    const float* bv     = (const float*)d_in[7];
    const float* Wo     = (const float*)d_in[8];
    const float* bo     = (const float*)d_in[9];
    const float* gamma  = (const float*)d_in[10];
    const float* beta   = (const float*)d_in[11];
    float* out = (float*)d_out;

    float *x, *nb, *pmx, *psm;
    __nv_bfloat16 *xb, *qb, *kb, *vb, *cb, *wq, *wk, *wv, *wo;
    cudaGetSymbolAddress((void**)&x,   g_x);
    cudaGetSymbolAddress((void**)&nb,  g_nb);
    cudaGetSymbolAddress((void**)&pmx, g_pmx);
    cudaGetSymbolAddress((void**)&psm, g_psm);
    cudaGetSymbolAddress((void**)&xb,  g_xb);
    cudaGetSymbolAddress((void**)&qb,  g_qb);
    cudaGetSymbolAddress((void**)&kb,  g_kb);
    cudaGetSymbolAddress((void**)&vb,  g_vb);
    cudaGetSymbolAddress((void**)&cb,  g_cb);
    cudaGetSymbolAddress((void**)&wq,  g_wq);
    cudaGetSymbolAddress((void**)&wk,  g_wk);
    cudaGetSymbolAddress((void**)&wv,  g_wv);
    cudaGetSymbolAddress((void**)&wo,  g_wo);

    cudaFuncSetAttribute(gemm_qkv,
                         cudaFuncAttributeMaxDynamicSharedMemorySize, SMEM_BYTES);
    cudaFuncSetAttribute(gemm_wo_pool,
                         cudaFuncAttributeMaxDynamicSharedMemorySize, SMEM_BYTES);
    cudaFuncSetAttribute(flash_kernel,
                         cudaFuncAttributeMaxDynamicSharedMemorySize, FL_SMEM);

    // 1. embed (f32 + bf16), mask, fused weight conversion
    embed_kernel<<<N_B * N_L, 256>>>(tokens, emb, x, xb);
    mask_kernel<<<8, 1024>>>(tokens, nb);
    conv4_kernel<<<8192, 256>>>(Wq, Wk, Wv, Wo, wq, wk, wv, wo);

    // 2. fused Q/K/V projections -> bf16 (128x128 tiles, occ 3)
    dim3 gQKV(8, 64, 3);
    gemm_qkv<<<gQKV, 256, SMEM_BYTES>>>(xb, wq, wk, wv, bq, bk, bv, qb, kb, vb);

    // 3-5. fused flash attention -> bf16 ctx
    flash_kernel<<<dim3(8, 64), 256, FL_SMEM>>>(qb, kb, vb, nb, cb);

    // 6. Wo GEMM + residual + pooling partials (r never written to gmem)
    dim3 gWo(8, 64, 1);
    gemm_wo_pool<<<gWo, 256, SMEM_BYTES>>>(cb, wo, bo, x, pmx, psm);

    // 7. fused reduce + layernorm
    ln_kernel<<<8, 256>>>(pmx, psm, gamma, beta, out);
}

// round 17
// speedup vs baseline: 1.1453x; 1.1453x over previous
#include <cuda_runtime.h>
#include <cuda_bf16.h>
#include <math.h>

// Shapes (fixed): B=8, L=1024, D=1024, H=8, DH=128, BH=64
#define N_B    8
#define N_L    1024
#define N_D    1024
#define SCALE_F 0.25f
#define EPS_F   1e-5f
#define LOG2E_F 1.4426950408889634f

// ---------------------------------------------------------------------------
// Scratch
// ---------------------------------------------------------------------------
__device__ float g_x[8u * 1024u * 1024u];     // embedded input (f32, residual)
__device__ float g_nb[8 * 1024];              // -inf mask bias
__device__ float g_pmx[8 * 8 * 1024];         // pool partial max [b][slice][d]
__device__ float g_psm[8 * 8 * 1024];         // pool partial sum

__device__ __nv_bfloat16 g_xb[8u * 1024u * 1024u];   // x bf16
__device__ __nv_bfloat16 g_qb[8u * 1024u * 1024u];   // Q bf16
__device__ __nv_bfloat16 g_kb[8u * 1024u * 1024u];   // K bf16
__device__ __nv_bfloat16 g_vb[8u * 1024u * 1024u];   // V bf16
__device__ __nv_bfloat16 g_cb[8u * 1024u * 1024u];   // ctx bf16
__device__ __nv_bfloat16 g_wq[1024 * 1024];
__device__ __nv_bfloat16 g_wk[1024 * 1024];
__device__ __nv_bfloat16 g_wv[1024 * 1024];
__device__ __nv_bfloat16 g_wo[1024 * 1024];

// ---------------------------------------------------------------------------
// Helpers
// ---------------------------------------------------------------------------
__device__ __forceinline__ void cpa16(void* dst_smem, const void* src_gmem) {
    unsigned d = (unsigned)__cvta_generic_to_shared(dst_smem);
    asm volatile("cp.async.cg.shared.global [%0], [%1], 16;\n"
                 :: "r"(d), "l"(src_gmem));
}

__device__ __forceinline__ float blockSum(float v) {
    __shared__ float sh[32];
    int lane = threadIdx.x & 31, wid = threadIdx.x >> 5;
    #pragma unroll
    for (int o = 16; o > 0; o >>= 1) v += __shfl_xor_sync(0xffffffffu, v, o);
    if (lane == 0) sh[wid] = v;
    __syncthreads();
    int nw = blockDim.x >> 5;
    float r = (threadIdx.x < (unsigned)nw) ? sh[threadIdx.x] : 0.0f;
    if (wid == 0) {
        #pragma unroll
        for (int o = 16; o > 0; o >>= 1) r += __shfl_xor_sync(0xffffffffu, r, o);
        if (lane == 0) sh[0] = r;
    }
    __syncthreads();
    float out = sh[0];
    __syncthreads();
    return out;
}

// ---------------------------------------------------------------------------
// Fused prologue: blocks [0,8192) embed (+mask), blocks [8192,16384) convert
// the 4 weight matrices to bf16.
// ---------------------------------------------------------------------------
__global__ void prologue_kernel(const int* __restrict__ tokens,
                                const float* __restrict__ emb,
                                float* __restrict__ x,
                                __nv_bfloat16* __restrict__ xb,
                                float* __restrict__ nb,
                                const float* __restrict__ s0, const float* __restrict__ s1,
                                const float* __restrict__ s2, const float* __restrict__ s3,
                                __nv_bfloat16* __restrict__ d0, __nv_bfloat16* __restrict__ d1,
                                __nv_bfloat16* __restrict__ d2, __nv_bfloat16* __restrict__ d3) {
    if (blockIdx.x < 8192) {
        int row = blockIdx.x;
        int tok = tokens[row];
        if (threadIdx.x == 0)
            nb[row] = (tok == 0) ? -INFINITY : 0.0f;
        float4 v = ((const float4*)(emb + (long)tok * N_D))[threadIdx.x];
        ((float4*)(x + (long)row * N_D))[threadIdx.x] = v;
        __nv_bfloat162* db = (__nv_bfloat162*)(xb + (long)row * N_D);
        db[2 * threadIdx.x]     = __nv_bfloat162(__float2bfloat16(v.x), __float2bfloat16(v.y));
        db[2 * threadIdx.x + 1] = __nv_bfloat162(__float2bfloat16(v.z), __float2bfloat16(v.w));
    } else {
        int blk = blockIdx.x - 8192;
        int w = blk >> 11;
        const float* src = (w == 0) ? s0 : (w == 1) ? s1 : (w == 2) ? s2 : s3;
        __nv_bfloat16* dst = (w == 0) ? d0 : (w == 1) ? d1 : (w == 2) ? d2 : d3;
        int i = (blk & 2047) * blockDim.x + threadIdx.x;
        float2 v = ((const float2*)src)[i];
        ((__nv_bfloat162*)dst)[i] =
            __nv_bfloat162(__float2bfloat16(v.x), __float2bfloat16(v.y));
    }
}

// ---------------------------------------------------------------------------
// bf16 MMA + ldmatrix
// ---------------------------------------------------------------------------
#define MMA_BF16(d, a, b)                                                     \
    asm volatile(                                                             \
        "mma.sync.aligned.m16n8k16.row.col.f32.bf16.bf16.f32 "                \
        "{%0,%1,%2,%3},{%4,%5,%6,%7},{%8,%9},{%0,%1,%2,%3};"                  \
        : "+f"((d)[0]), "+f"((d)[1]), "+f"((d)[2]), "+f"((d)[3])              \
        : "r"((a)[0]), "r"((a)[1]), "r"((a)[2]), "r"((a)[3]),                 \
          "r"((b)[0]), "r"((b)[1]))

#define LDSM_X4(r0, r1, r2, r3, addr)                                         \
    asm volatile("ldmatrix.sync.aligned.m8n8.x4.shared.b16 {%0,%1,%2,%3}, [%4];" \
                 : "=r"(r0), "=r"(r1), "=r"(r2), "=r"(r3) : "r"(addr))

#define LDSM_X4T(r0, r1, r2, r3, addr)                                        \
    asm volatile("ldmatrix.sync.aligned.m8n8.x4.trans.shared.b16 {%0,%1,%2,%3}, [%4];" \
                 : "=r"(r0), "=r"(r1), "=r"(r2), "=r"(r3) : "r"(addr))

// ---------------------------------------------------------------------------
// GEMM SMEM geometry: 128x128 tile, K-chunk 32, 4-stage ring (R15 config)
// ---------------------------------------------------------------------------
#define A_LDH   40
#define BNN_LDH 136
#define A_H     (128 * A_LDH)
#define B_H     5120
#define STG_H   (A_H + B_H)
#define NSTG    4
#define SMEM_BYTES (NSTG * STG_H * 2)     // 81920 B

// Shared mainloop: 128x128 tile into acc[4][4][4], warp tile 64x32.
#define GEMM_MAINLOOP(Aptr, Bptr, row0, col0, K)                              \
    int KT = (K) >> 5;                                                        \
    auto load_tile = [&](int kt, int buf) {                                   \
        __nv_bfloat16* Asb = sm + buf * STG_H;                                \
        __nv_bfloat16* Bsb = Asb + A_H;                                       \
        int k0 = kt << 5;                                                     \
        _Pragma("unroll")                                                     \
        for (int p = 0; p < 2; p++) {                                         \
            int idx = p * 256 + tid;                                          \
            int rr = idx >> 2, cc = (idx & 3) << 3;                           \
            cpa16(Asb + rr * A_LDH + cc, (Aptr) + (long)((row0) + rr) * (K) + k0 + cc); \
        }                                                                     \
        _Pragma("unroll")                                                     \
        for (int p = 0; p < 2; p++) {                                         \
            int idx = p * 256 + tid;                                          \
            int rr = idx >> 4, cc = (idx & 15) << 3;                          \
            cpa16(Bsb + rr * BNN_LDH + cc, (Bptr) + (long)(k0 + rr) * 1024 + (col0) + cc); \
        }                                                                     \
    };                                                                        \
    float acc[4][4][4];                                                       \
    _Pragma("unroll")                                                         \
    for (int i = 0; i < 4; i++)                                               \
        _Pragma("unroll")                                                     \
        for (int j = 0; j < 4; j++)                                           \
            _Pragma("unroll")                                                 \
            for (int t = 0; t < 4; t++) acc[i][j][t] = 0.0f;                  \
    load_tile(0, 0);                                                          \
    asm volatile("cp.async.commit_group;\n" ::);                              \
    load_tile(1, 1);                                                          \
    asm volatile("cp.async.commit_group;\n" ::);                              \
    load_tile(2, 2);                                                          \
    asm volatile("cp.async.commit_group;\n" ::);                              \
    for (int kt = 0; kt < KT; kt++) {                                         \
        asm volatile("cp.async.wait_group 2;\n" ::);                          \
        __syncthreads();                                                      \
        if (kt + 3 < KT) load_tile(kt + 3, (kt + 3) & 3);                     \
        asm volatile("cp.async.commit_group;\n" ::);                          \
        __nv_bfloat16* Asb = sm + (kt & 3) * STG_H;                           \
        unsigned AsU = (unsigned)__cvta_generic_to_shared(Asb);               \
        unsigned BsU = (unsigned)__cvta_generic_to_shared(Asb + A_H);         \
        _Pragma("unroll")                                                     \
        for (int ks = 0; ks < 2; ks++) {                                      \
            int k0h = ks * 16;                                                \
            unsigned afr[4][4];                                               \
            _Pragma("unroll")                                                 \
            for (int i = 0; i < 4; i++) {                                     \
                int rr = warpRow * 64 + i * 16 + (lane & 15);                 \
                unsigned ad = AsU + (rr * A_LDH + k0h + ((lane >> 4) << 3)) * 2; \
                LDSM_X4(afr[i][0], afr[i][1], afr[i][2], afr[i][3], ad);      \
            }                                                                 \
            unsigned bfr[4][2];                                               \
            _Pragma("unroll")                                                 \
            for (int j2 = 0; j2 < 2; j2++) {                                  \
                int n0 = warpCol * 32 + j2 * 16;                              \
                int rr = k0h + (((lane >> 3) & 1) << 3) + (lane & 7);         \
                int cc = n0 + ((lane >> 4) << 3);                             \
                unsigned ad = BsU + (rr * BNN_LDH + cc) * 2;                  \
                LDSM_X4T(bfr[2 * j2][0], bfr[2 * j2][1],                      \
                         bfr[2 * j2 + 1][0], bfr[2 * j2 + 1][1], ad);         \
            }                                                                 \
            _Pragma("unroll")                                                 \
            for (int i = 0; i < 4; i++)                                       \
                _Pragma("unroll")                                             \
                for (int j = 0; j < 4; j++)                                   \
                    MMA_BF16(acc[i][j], afr[i], bfr[j]);                      \
        }                                                                     \
    }

// ---------------------------------------------------------------------------
// Fused QKV GEMM: z selects (W, bias, C); bf16 output. 128x128 tile.
// ---------------------------------------------------------------------------
__global__ void __launch_bounds__(256)
gemm_qkv(const __nv_bfloat16* __restrict__ A,
         const __nv_bfloat16* B0, const __nv_bfloat16* B1, const __nv_bfloat16* B2,
         const float* bias0, const float* bias1, const float* bias2,
         __nv_bfloat16* C0, __nv_bfloat16* C1, __nv_bfloat16* C2) {
    extern __shared__ __nv_bfloat16 sm[];
    int z = blockIdx.z;
    const __nv_bfloat16* B = (z == 0) ? B0 : (z == 1) ? B1 : B2;
    const float* bias      = (z == 0) ? bias0 : (z == 1) ? bias1 : bias2;
    __nv_bfloat16* C       = (z == 0) ? C0 : (z == 1) ? C1 : C2;

    int tid = threadIdx.x;
    int lane = tid & 31, wid = tid >> 5;
    int warpRow = wid >> 2, warpCol = wid & 3;
    int grp = lane >> 2, qid = lane & 3;
    int row0 = blockIdx.y * 128;
    int col0 = blockIdx.x * 128;

    GEMM_MAINLOOP(A, B, row0, col0, 1024)

    #pragma unroll
    for (int i = 0; i < 4; i++) {
        int r = row0 + warpRow * 64 + i * 16 + grp;
        #pragma unroll
        for (int j = 0; j < 4; j++) {
            int c = col0 + warpCol * 32 + j * 8 + 2 * qid;
            float2 bb = *(const float2*)(bias + c);
            *(__nv_bfloat162*)(C + (long)r * 1024 + c) =
                __floats2bfloat162_rn(acc[i][j][0] + bb.x, acc[i][j][1] + bb.y);
            *(__nv_bfloat162*)(C + (long)(r + 8) * 1024 + c) =
                __floats2bfloat162_rn(acc[i][j][2] + bb.x, acc[i][j][3] + bb.y);
        }
    }
}

// ---------------------------------------------------------------------------
// Wo GEMM + residual + fused pooling partials (r never hits gmem).
//   128x128 tile; grid (8, 64); blockIdx.y: b = y>>3, slice = y&7.
// ---------------------------------------------------------------------------
__global__ void __launch_bounds__(256)
gemm_wo_pool(const __nv_bfloat16* __restrict__ A, const __nv_bfloat16* __restrict__ B,
             const float* __restrict__ bias, const float* __restrict__ res,
             float* __restrict__ pmx, float* __restrict__ psm) {
    extern __shared__ __nv_bfloat16 sm[];

    int tid = threadIdx.x;
    int lane = tid & 31, wid = tid >> 5;
    int warpRow = wid >> 2, warpCol = wid & 3;
    int grp = lane >> 2, qid = lane & 3;
    int row0 = blockIdx.y * 128;
    int col0 = blockIdx.x * 128;

    GEMM_MAINLOOP(A, B, row0, col0, 1024)

    // epilogue: v = acc + bias + res; per-column (max,sum) over 128 rows
    __syncthreads();                       // tile ring no longer in use
    float* sPm = (float*)sm;               // [2][128]
    float* sPs = (float*)sm + 256;         // [2][128]

    #pragma unroll
    for (int j = 0; j < 4; j++) {
        int c = col0 + warpCol * 32 + j * 8 + 2 * qid;
        float2 bb = *(const float2*)(bias + c);
        float m0 = -INFINITY, m1 = -INFINITY, s0 = 0.0f, s1 = 0.0f;
        #pragma unroll
        for (int i = 0; i < 4; i++) {
            int r = row0 + warpRow * 64 + i * 16 + grp;
            float2 r0v = *(const float2*)(res + (long)r * 1024 + c);
            float2 r1v = *(const float2*)(res + (long)(r + 8) * 1024 + c);
            float v00 = acc[i][j][0] + bb.x + r0v.x;
            float v01 = acc[i][j][1] + bb.y + r0v.y;
            float v10 = acc[i][j][2] + bb.x + r1v.x;
            float v11 = acc[i][j][3] + bb.y + r1v.y;
            m0 = fmaxf(m0, fmaxf(v00, v10));
            m1 = fmaxf(m1, fmaxf(v01, v11));
            s0 += v00 + v10;
            s1 += v01 + v11;
        }
        #pragma unroll
        for (int o = 4; o <= 16; o <<= 1) {
            m0 = fmaxf(m0, __shfl_xor_sync(0xffffffffu, m0, o));
            m1 = fmaxf(m1, __shfl_xor_sync(0xffffffffu, m1, o));
            s0 += __shfl_xor_sync(0xffffffffu, s0, o);
            s1 += __shfl_xor_sync(0xffffffffu, s1, o);
        }
        if (grp == 0) {
            int lc = warpCol * 32 + j * 8 + 2 * qid;
            sPm[warpRow * 128 + lc]     = m0;
            sPm[warpRow * 128 + lc + 1] = m1;
            sPs[warpRow * 128 + lc]     = s0;
            sPs[warpRow * 128 + lc + 1] = s1;
        }
    }
    __syncthreads();

    if (tid < 128) {
        int b = blockIdx.y >> 3, sl = blockIdx.y & 7;
        float m = fmaxf(sPm[tid], sPm[128 + tid]);
        float s = sPs[tid] + sPs[128 + tid];
        long o = (((long)(b << 3) + sl) << 10) + col0 + tid;
        pmx[o] = m;
        psm[o] = s;
    }
}

// ---------------------------------------------------------------------------
// Fused flash attention, 64-row KV tiles, 2 CTAs/SM (unchanged)
// ---------------------------------------------------------------------------
#define FL_LDH     136
#define FL_Q_H     (128 * FL_LDH)
#define FL_KV_H    (64 * FL_LDH)
#define FL_SMEM    ((FL_Q_H + 4 * FL_KV_H) * 2)

__global__ void __launch_bounds__(256, 2)
flash_kernel(const __nv_bfloat16* __restrict__ Q,
             const __nv_bfloat16* __restrict__ K,
             const __nv_bfloat16* __restrict__ V,
             const float* __restrict__ nb,
             __nv_bfloat16* __restrict__ Octx) {
    extern __shared__ __nv_bfloat16 fsm[];
    __nv_bfloat16* Qs = fsm;
    __nv_bfloat16* Ks = fsm + FL_Q_H;
    __nv_bfloat16* Vs = fsm + FL_Q_H + 2 * FL_KV_H;

    int tid = threadIdx.x;
    int lane = tid & 31, wid = tid >> 5;
    int grp = lane >> 2, qid = lane & 3;
    int m0 = wid * 16;

    int bh = blockIdx.y;
    int q0 = blockIdx.x * 128;
    const __nv_bfloat16* Qg = Q + (long)bh * 131072 + (long)q0 * 128;
    const __nv_bfloat16* Kg = K + (long)bh * 131072;
    const __nv_bfloat16* Vg = V + (long)bh * 131072;
    const float* nbr = nb + ((bh & 7) << 10);
    __nv_bfloat16* Cg = Octx + (long)bh * 131072 + (long)q0 * 128;

    auto loadKV = [&](int kt, int stg) {
        const __nv_bfloat16* Kt = Kg + (long)kt * 8192;
        const __nv_bfloat16* Vt = Vg + (long)kt * 8192;
        __nv_bfloat16* Kd = Ks + stg * FL_KV_H;
        __nv_bfloat16* Vd = Vs + stg * FL_KV_H;
        #pragma unroll
        for (int p = 0; p < 4; p++) {
            int idx = p * 256 + tid;
            int r = idx >> 4, cc = (idx & 15) << 3;
            cpa16(Kd + r * FL_LDH + cc, Kt + r * 128 + cc);
        }
        #pragma unroll
        for (int p = 0; p < 4; p++) {
            int idx = p * 256 + tid;
            int r = idx >> 4, cc = (idx & 15) << 3;
            cpa16(Vd + r * FL_LDH + cc, Vt + r * 128 + cc);
        }
    };

    #pragma unroll
    for (int p = 0; p < 8; p++) {
        int idx = p * 256 + tid;
        int r = idx >> 4, cc = (idx & 15) << 3;
        cpa16(Qs + r * FL_LDH + cc, Qg + r * 128 + cc);
    }
    loadKV(0, 0);
    asm volatile("cp.async.commit_group;\n" ::);

    float o[16][4];
    #pragma unroll
    for (int j = 0; j < 16; j++)
        #pragma unroll
        for (int t = 0; t < 4; t++) o[j][t] = 0.0f;
    float mrow0 = -1e30f, mrow1 = -1e30f;
    float lrow0 = 0.0f,  lrow1 = 0.0f;

    unsigned QsU = (unsigned)__cvta_generic_to_shared(Qs);

    #pragma unroll 1
    for (int kt = 0; kt < 16; kt++) {
        int stg = kt & 1;
        if (kt < 15) loadKV(kt + 1, stg ^ 1);
        asm volatile("cp.async.commit_group;\n" ::);
        asm volatile("cp.async.wait_group 1;\n" ::);
        __syncthreads();

        unsigned KsU = (unsigned)__cvta_generic_to_shared(Ks + stg * FL_KV_H);
        unsigned VsU = (unsigned)__cvta_generic_to_shared(Vs + stg * FL_KV_H);

        float s[8][4];
        #pragma unroll
        for (int j = 0; j < 8; j++)
            #pragma unroll
            for (int t = 0; t < 4; t++) s[j][t] = 0.0f;

        #pragma unroll
        for (int kf = 0; kf < 8; kf++) {
            unsigned aq[4];
            {
                int r = m0 + (lane & 15);
                int c = kf * 16 + ((lane >> 4) << 3);
                LDSM_X4(aq[0], aq[1], aq[2], aq[3], QsU + (r * FL_LDH + c) * 2);
            }
            #pragma unroll
            for (int j2 = 0; j2 < 4; j2++) {
                unsigned bq[4];
                int rn = j2 * 16 + ((lane >> 4) << 3) + (lane & 7);
                int ck = kf * 16 + (((lane >> 3) & 1) << 3);
                LDSM_X4(bq[0], bq[1], bq[2], bq[3], KsU + (rn * FL_LDH + ck) * 2);
                MMA_BF16(s[2 * j2],     aq, bq);
                MMA_BF16(s[2 * j2 + 1], aq, (bq + 2));
            }
        }

        int kb = kt << 6;
        float mx0 = mrow0, mx1 = mrow1;
        #pragma unroll
        for (int j = 0; j < 8; j++) {
            float2 msk = *(const float2*)(nbr + kb + j * 8 + 2 * qid);
            s[j][0] = fmaf(s[j][0], SCALE_F, msk.x);
            s[j][1] = fmaf(s[j][1], SCALE_F, msk.y);
            s[j][2] = fmaf(s[j][2], SCALE_F, msk.x);
            s[j][3] = fmaf(s[j][3], SCALE_F, msk.y);
            mx0 = fmaxf(mx0, fmaxf(s[j][0], s[j][1]));
            mx1 = fmaxf(mx1, fmaxf(s[j][2], s[j][3]));
        }
        mx0 = fmaxf(mx0, __shfl_xor_sync(0xffffffffu, mx0, 1));
        mx0 = fmaxf(mx0, __shfl_xor_sync(0xffffffffu, mx0, 2));
        mx1 = fmaxf(mx1, __shfl_xor_sync(0xffffffffu, mx1, 1));
        mx1 = fmaxf(mx1, __shfl_xor_sync(0xffffffffu, mx1, 2));

        float al0 = exp2f((mrow0 - mx0) * LOG2E_F);
        float al1 = exp2f((mrow1 - mx1) * LOG2E_F);
        mrow0 = mx0; mrow1 = mx1;

        float r0 = 0.0f, r1 = 0.0f;
        #pragma unroll
        for (int j = 0; j < 8; j++) {
            s[j][0] = exp2f((s[j][0] - mx0) * LOG2E_F);
            s[j][1] = exp2f((s[j][1] - mx0) * LOG2E_F);
            s[j][2] = exp2f((s[j][2] - mx1) * LOG2E_F);
            s[j][3] = exp2f((s[j][3] - mx1) * LOG2E_F);
            r0 += s[j][0] + s[j][1];
            r1 += s[j][2] + s[j][3];
        }
        #pragma unroll
        for (int j = 0; j < 16; j++) {
            o[j][0] *= al0; o[j][1] *= al0;
            o[j][2] *= al1; o[j][3] *= al1;
        }
        lrow0 = lrow0 * al0 + r0;
        lrow1 = lrow1 * al1 + r1;

        #pragma unroll
        for (int t = 0; t < 4; t++) {
            unsigned ap[4];
            __nv_bfloat162 p0 = __floats2bfloat162_rn(s[2 * t][0],     s[2 * t][1]);
            __nv_bfloat162 p1 = __floats2bfloat162_rn(s[2 * t][2],     s[2 * t][3]);
            __nv_bfloat162 p2 = __floats2bfloat162_rn(s[2 * t + 1][0], s[2 * t + 1][1]);
            __nv_bfloat162 p3 = __floats2bfloat162_rn(s[2 * t + 1][2], s[2 * t + 1][3]);
            ap[0] = *(unsigned*)&p0;
            ap[1] = *(unsigned*)&p1;
            ap[2] = *(unsigned*)&p2;
            ap[3] = *(unsigned*)&p3;
            #pragma unroll
            for (int j2 = 0; j2 < 8; j2++) {
                unsigned bv[4];
                int rk = t * 16 + (((lane >> 3) & 1) << 3) + (lane & 7);
                int cn = j2 * 16 + ((lane >> 4) << 3);
                LDSM_X4T(bv[0], bv[1], bv[2], bv[3], VsU + (rk * FL_LDH + cn) * 2);
                MMA_BF16(o[2 * j2],     ap, bv);
                MMA_BF16(o[2 * j2 + 1], ap, (bv + 2));
            }
        }
        __syncthreads();
    }

    lrow0 += __shfl_xor_sync(0xffffffffu, lrow0, 1);
    lrow0 += __shfl_xor_sync(0xffffffffu, lrow0, 2);
    lrow1 += __shfl_xor_sync(0xffffffffu, lrow1, 1);
    lrow1 += __shfl_xor_sync(0xffffffffu, lrow1, 2);
    float inv0 = 1.0f / lrow0;
    float inv1 = 1.0f / lrow1;

    int r0i = m0 + grp, r1i = m0 + grp + 8;
    #pragma unroll
    for (int j = 0; j < 16; j++) {
        int c = j * 8 + 2 * qid;
        *(__nv_bfloat162*)(Cg + (long)r0i * 128 + c) =
            __floats2bfloat162_rn(o[j][0] * inv0, o[j][1] * inv0);
        *(__nv_bfloat162*)(Cg + (long)r1i * 128 + c) =
            __floats2bfloat162_rn(o[j][2] * inv1, o[j][3] * inv1);
    }
}

// ---------------------------------------------------------------------------
// Fused partial-reduce + LayerNorm
// ---------------------------------------------------------------------------
__global__ void __launch_bounds__(256)
ln_kernel(const float* __restrict__ pmx, const float* __restrict__ psm,
          const float* __restrict__ gamma, const float* __restrict__ beta,
          float* __restrict__ out) {
    int b = blockIdx.x, tid = threadIdx.x;
    float av[8];
    #pragma unroll
    for (int i = 0; i < 8; i++) {
        int k = tid + i * 256;
        if (k < 1024) {
            float mx = -INFINITY;
            #pragma unroll
            for (int sl = 0; sl < 8; sl++)
                mx = fmaxf(mx, pmx[(((b << 3) + sl) << 10) + k]);
            av[i] = mx;
        } else {
            int d = k - 1024;
            float sm = 0.0f;
            #pragma unroll
            for (int sl = 0; sl < 8; sl++)
                sm += psm[(((b << 3) + sl) << 10) + d];
            av[i] = sm * (1.0f / 1024.0f);
        }
    }
    float s = 0.0f;
    #pragma unroll
    for (int i = 0; i < 8; i++) s += av[i];
    s = blockSum(s);
    float mu = s * (1.0f / 2048.0f);
    float vs = 0.0f;
    #pragma unroll
    for (int i = 0; i < 8; i++) {
        float d = av[i] - mu;
        vs += d * d;
    }
    vs = blockSum(vs);
    float inv = rsqrtf(vs * (1.0f / 2048.0f) + EPS_F);
    #pragma unroll
    for (int i = 0; i < 8; i++) {
        int k = tid + i * 256;
        out[b * 2048 + k] = (av[i] - mu) * inv * gamma[k] + beta[k];
    }
}

// ---------------------------------------------------------------------------
// Launch
// ---------------------------------------------------------------------------
extern "C" void kernel_launch(void* const* d_in, const int* in_sizes, int n_in,
                              void* d_out, int out_size) {
    const int*   tokens = (const int*)  d_in[0];
    const float* emb    = (const float*)d_in[1];
    const float* Wq     = (const float*)d_in[2];
    const float* bq     = (const float*)d_in[3];
    const float* Wk     = (const float*)d_in[4];
    const float* bk     = (const float*)d_in[5];
    const float* Wv     = (const float*)d_in[6];
    const float* bv     = (const float*)d_in[7];
    const float* Wo     = (const float*)d_in[8];
    const float* bo     = (const float*)d_in[9];
    const float* gamma  = (const float*)d_in[10];
    const float* beta   = (const float*)d_in[11];
    float* out = (float*)d_out;

    float *x, *nb, *pmx, *psm;
    __nv_bfloat16 *xb, *qb, *kb, *vb, *cb, *wq, *wk, *wv, *wo;
    cudaGetSymbolAddress((void**)&x,   g_x);
    cudaGetSymbolAddress((void**)&nb,  g_nb);
    cudaGetSymbolAddress((void**)&pmx, g_pmx);
    cudaGetSymbolAddress((void**)&psm, g_psm);
    cudaGetSymbolAddress((void**)&xb,  g_xb);
    cudaGetSymbolAddress((void**)&qb,  g_qb);
    cudaGetSymbolAddress((void**)&kb,  g_kb);
    cudaGetSymbolAddress((void**)&vb,  g_vb);
    cudaGetSymbolAddress((void**)&cb,  g_cb);
    cudaGetSymbolAddress((void**)&wq,  g_wq);
    cudaGetSymbolAddress((void**)&wk,  g_wk);
    cudaGetSymbolAddress((void**)&wv,  g_wv);
    cudaGetSymbolAddress((void**)&wo,  g_wo);

    cudaFuncSetAttribute(gemm_qkv,
                         cudaFuncAttributeMaxDynamicSharedMemorySize, SMEM_BYTES);
    cudaFuncSetAttribute(gemm_wo_pool,
                         cudaFuncAttributeMaxDynamicSharedMemorySize, SMEM_BYTES);
    cudaFuncSetAttribute(flash_kernel,
                         cudaFuncAttributeMaxDynamicSharedMemorySize, FL_SMEM);

    // 1. fused prologue: embed (f32+bf16) + mask + 4-weight convert, one launch
    prologue_kernel<<<16384, 256>>>(tokens, emb, x, xb, nb,
                                    Wq, Wk, Wv, Wo, wq, wk, wv, wo);

    // 2. fused Q/K/V projections -> bf16 (128x128 tiles, 4-stage ring, occ 2)
    dim3 gQKV(8, 64, 3);
    gemm_qkv<<<gQKV, 256, SMEM_BYTES>>>(xb, wq, wk, wv, bq, bk, bv, qb, kb, vb);

    // 3-5. fused flash attention -> bf16 ctx
    flash_kernel<<<dim3(8, 64), 256, FL_SMEM>>>(qb, kb, vb, nb, cb);

    // 6. Wo GEMM + residual + pooling partials (r never written to gmem)
    dim3 gWo(8, 64, 1);
    gemm_wo_pool<<<gWo, 256, SMEM_BYTES>>>(cb, wo, bo, x, pmx, psm);

    // 7. fused reduce + layernorm
    ln_kernel<<<8, 256>>>(pmx, psm, gamma, beta, out);
}